// round 16
// baseline (speedup 1.0000x reference)
#include <cuda_runtime.h>
#include <cuda_fp16.h>
#include <cstdint>

#define N_NODES 262144
#define C 64
#define K 16
#define NCLS 40

#define WARPS 16
#define THREADS (WARPS * 32)
#define NODES_PER_BLOCK 128
#define NODES_PER_WARP 8

// ---- A-fragment feat storage: 16 ktiles (h:0-7, rel:8-15), 128r x 8c fp16, pad 2064 ----
#define KTS 2064
#define SMEM_BYTES (16 * KTS)       // 33024; 3 blocks/SM = 99KB <= 228KB

// prologue grid split
#define CPE_BLOCKS 2048
#define FUSE_BLOCKS 21
#define PRO_BLOCKS (CPE_BLOCKS + FUSE_BLOCKS + 1)

// ---- device scratch (allocation-free rule) ----
__device__ __align__(256) static __half d_hh[N_NODES * C];     // 32 MB fp16 h (L2-resident)
__device__ __align__(8)  static float d_bf[NCLS];
// fp16 k16 B fragments: cell=(kt2*5+nt)*32+lane, 4 u16/cell
__device__ __align__(16) static uint16_t d_Bfrag[1280 * 4];    // 10240 B
__device__ static int d_idx64;

// ---------- helpers ----------
__device__ __forceinline__ void mma16f(float* c, uint32_t a0, uint32_t a1, uint32_t a2,
                                       uint32_t a3, uint32_t b0, uint32_t b1) {
    asm volatile("mma.sync.aligned.m16n8k16.row.col.f32.f16.f16.f32 "
                 "{%0,%1,%2,%3}, {%4,%5,%6,%7}, {%8,%9}, {%0,%1,%2,%3};"
                 : "+f"(c[0]), "+f"(c[1]), "+f"(c[2]), "+f"(c[3])
                 : "r"(a0), "r"(a1), "r"(a2), "r"(a3), "r"(b0), "r"(b1));
}
__device__ __forceinline__ uint32_t h2max_u(uint32_t a, uint32_t b) {
    uint32_t r;
    asm("max.f16x2 %0, %1, %2;" : "=r"(r) : "r"(a), "r"(b));
    return r;
}
__device__ __forceinline__ uint32_t h2sub_u(uint32_t a, uint32_t b) {  // a - b packed fp16
    uint32_t r;
    asm("sub.rn.f16x2 %0, %1, %2;" : "=r"(r) : "r"(a), "r"(b));
    return r;
}

// ---------- prologue: CPE (blocks 0..2047) + fuse_w (21 blocks) + detect (1) ----------
__global__ void prologue_kernel(const float4* __restrict__ x4,
                                const float* __restrict__ cw,
                                const float* __restrict__ cb,
                                const float* __restrict__ gw,
                                const float* __restrict__ gb,
                                const float* __restrict__ ow,
                                const float* __restrict__ ob,
                                const unsigned int* __restrict__ nbrw) {
    if (blockIdx.x < CPE_BLOCKS) {
        // ---- CPE depthwise conv (kernel 3 over node dim) + residual; fp16 output ----
        const int idx = blockIdx.x * 256 + threadIdx.x;
        const int q = idx & 15;
        const int n0 = (idx >> 4) * 8;
        const int c0 = q * 4;
        const float w0x = __ldg(cw + (c0+0)*3+0), w1x = __ldg(cw + (c0+0)*3+1), w2x = __ldg(cw + (c0+0)*3+2);
        const float w0y = __ldg(cw + (c0+1)*3+0), w1y = __ldg(cw + (c0+1)*3+1), w2y = __ldg(cw + (c0+1)*3+2);
        const float w0z = __ldg(cw + (c0+2)*3+0), w1z = __ldg(cw + (c0+2)*3+1), w2z = __ldg(cw + (c0+2)*3+2);
        const float w0w = __ldg(cw + (c0+3)*3+0), w1w = __ldg(cw + (c0+3)*3+1), w2w = __ldg(cw + (c0+3)*3+2);
        const float bx = __ldg(cb+c0+0), by = __ldg(cb+c0+1), bz = __ldg(cb+c0+2), bw = __ldg(cb+c0+3);

        const float4 zero = make_float4(0.f, 0.f, 0.f, 0.f);
        float4 a = (n0 > 0) ? __ldcs(x4 + (n0 - 1) * 16 + q) : zero;
        float4 b = __ldcs(x4 + n0 * 16 + q);
        uint2* hh2 = reinterpret_cast<uint2*>(d_hh);
        #pragma unroll
        for (int r = 0; r < 8; ++r) {
            const int n = n0 + r;
            const float4 nx = (n + 1 < N_NODES) ? __ldcs(x4 + (n + 1) * 16 + q) : zero;
            float4 o;
            o.x = b.x + (a.x*w0x + b.x*w1x + nx.x*w2x + bx);
            o.y = b.y + (a.y*w0y + b.y*w1y + nx.y*w2y + by);
            o.z = b.z + (a.z*w0z + b.z*w1z + nx.z*w2z + bz);
            o.w = b.w + (a.w*w0w + b.w*w1w + nx.w*w2w + bw);
            const __half2 p0 = __floats2half2_rn(o.x, o.y);
            const __half2 p1 = __floats2half2_rn(o.z, o.w);
            uint2 u;
            u.x = *reinterpret_cast<const uint32_t*>(&p0);
            u.y = *reinterpret_cast<const uint32_t*>(&p1);
            hh2[n * 16 + q] = u;
            a = b; b = nx;
        }
        return;
    }
    if (blockIdx.x == CPE_BLOCKS + FUSE_BLOCKS) {
        // ---- detect whether nbr_idx is int64 (odd 32-bit words all zero) ----
        __shared__ int any;
        if (threadIdx.x == 0) any = 0;
        __syncthreads();
        if (nbrw[2 * threadIdx.x + 1] != 0u) any = 1;
        __syncthreads();
        if (threadIdx.x == 0) d_idx64 = (any ? 0 : 1);
        return;
    }
    // ---- fuse grapher into head; emit fp16 k16 B-fragment cells ----
    const int t = (blockIdx.x - CPE_BLOCKS) * 256 + threadIdx.x;
    if (t < 2 * C * NCLS) {
        const int c = t / NCLS, j = t % NCLS;
        float acc = (c < C) ? ow[c * NCLS + j] : 0.f;
        #pragma unroll 8
        for (int d = 0; d < C; ++d) acc += gw[c * C + d] * ow[d * NCLS + j];
        const int kt2 = c >> 4, pairw = (c >> 3) & 1, nt = j >> 3;
        const int lane = (j & 7) * 4 + ((c & 7) >> 1);
        const int cell = (kt2 * 5 + nt) * 32 + lane;
        const __half hv = __float2half(acc);
        d_Bfrag[cell * 4 + pairw * 2 + (c & 1)] = *reinterpret_cast<const uint16_t*>(&hv);
    } else if (t < 2 * C * NCLS + NCLS) {
        const int j = t - 2 * C * NCLS;
        float acc = ob[j];
        for (int d = 0; d < C; ++d) acc += gb[d] * ow[d * NCLS + j];
        d_bf[j] = acc;
    }
}

// ---------- main kernel: fp16 gather -> fp16 A-frags -> mma f16 -> log_softmax ----------
__global__ __launch_bounds__(THREADS, 3) void main_kernel(const void* __restrict__ nbr,
                                                          float* __restrict__ out) {
    extern __shared__ __align__(16) char smem[];
    const int tid = threadIdx.x;
    const int warp = tid >> 5, lane = tid & 31;
    const __half* __restrict__ HH = d_hh;

    // ---- gather: half-warp = 1 node; lane owns channel quad q = lane&15 ----
    const int nodeBase = blockIdx.x * NODES_PER_BLOCK + warp * NODES_PER_WARP;
    const int is64 = d_idx64;
    const int q = lane & 15;
    const int half = lane >> 4;
    const int n0 = nodeBase + half;

    int idxs[4];
    if (is64) {
        const long long* p = (const long long*)nbr + (size_t)n0 * K + q;
        #pragma unroll
        for (int t = 0; t < 4; ++t) idxs[t] = (int)__ldcg(p + 2 * t * K);
    } else {
        const int* p = (const int*)nbr + n0 * K + q;
        #pragma unroll
        for (int t = 0; t < 4; ++t) idxs[t] = __ldcg(p + 2 * t * K);
    }

    const uint32_t baseC = (uint32_t)(q >> 1) * KTS
                         + (uint32_t)((warp >> 1) * 2 + (warp & 1)) * 128
                         + (uint32_t)(half * 4 + (q & 1) * 2) * 4;

    #pragma unroll
    for (int t = 0; t < 4; ++t) {
        const int myj = idxs[t];
        const uint2 hv = __ldcg((const uint2*)(HH + (n0 + 2 * t) * C) + q);
        const uint32_t ninf = 0xFBFFFBFFu;   // half2(-65504, -65504)
        // two 8-deep max trees (best measured schedule)
        uint32_t m0a = ninf, m0b = ninf, m1a = ninf, m1b = ninf;
        #pragma unroll
        for (int k = 0; k < K; k += 2) {
            const int j0 = __shfl_sync(0xffffffffu, myj, k, 16);
            const int j1 = __shfl_sync(0xffffffffu, myj, k + 1, 16);
            const uint2 u0 = __ldcg((const uint2*)(HH + j0 * C + q * 4));
            const uint2 u1 = __ldcg((const uint2*)(HH + j1 * C + q * 4));
            m0a = h2max_u(m0a, u0.x); m0b = h2max_u(m0b, u0.y);
            m1a = h2max_u(m1a, u1.x); m1b = h2max_u(m1b, u1.y);
        }
        // rel = max - h, packed fp16 (one rounding; h itself stored exactly)
        uint2 rel;
        rel.x = h2sub_u(h2max_u(m0a, m1a), hv.x);
        rel.y = h2sub_u(h2max_u(m0b, m1b), hv.y);

        const uint32_t base = baseC + (uint32_t)t * 32;
        *(uint2*)(smem + base)           = hv;      // ktiles 0..7  (h, exact)
        *(uint2*)(smem + 8 * KTS + base) = rel;     // ktiles 8..15 (rel)
    }
    __syncthreads();

    // ---- MMA: warps 0-7, m16n8k16 fp16; B frags via L1 LDG.64; direct-STG epilogue ----
    if (warp < 8) {
        float acc[5][4];
        #pragma unroll
        for (int nt = 0; nt < 5; ++nt)
            #pragma unroll
            for (int p = 0; p < 4; ++p) acc[nt][p] = 0.f;

        const char* fa = smem + (warp * 2) * 128 + lane * 4;
        const uint2* Bq = reinterpret_cast<const uint2*>(d_Bfrag) + lane;
        #pragma unroll
        for (int kt2 = 0; kt2 < 8; ++kt2) {
            const uint32_t a0 = *(const uint32_t*)(fa + (2 * kt2) * KTS);
            const uint32_t a1 = *(const uint32_t*)(fa + (2 * kt2) * KTS + 128);
            const uint32_t a2 = *(const uint32_t*)(fa + (2 * kt2 + 1) * KTS);
            const uint32_t a3 = *(const uint32_t*)(fa + (2 * kt2 + 1) * KTS + 128);
            #pragma unroll
            for (int nt = 0; nt < 5; ++nt) {
                const uint2 w = __ldg(Bq + (kt2 * 5 + nt) * 32);
                mma16f(acc[nt], a0, a1, a2, a3, w.x, w.y);
            }
        }

        // bias + per-row log_softmax (rows: rA = 16w + lane/4, rB = rA + 8)
        float lg[2][10];
        #pragma unroll
        for (int nt = 0; nt < 5; ++nt) {
            const float2 b = __ldg(reinterpret_cast<const float2*>(d_bf) + nt * 4 + (lane & 3));
            lg[0][2 * nt]     = acc[nt][0] + b.x;
            lg[0][2 * nt + 1] = acc[nt][1] + b.y;
            lg[1][2 * nt]     = acc[nt][2] + b.x;
            lg[1][2 * nt + 1] = acc[nt][3] + b.y;
        }
        float mA = lg[0][0], mB = lg[1][0];
        #pragma unroll
        for (int i = 1; i < 10; ++i) { mA = fmaxf(mA, lg[0][i]); mB = fmaxf(mB, lg[1][i]); }
        mA = fmaxf(mA, __shfl_xor_sync(0xffffffffu, mA, 1));
        mA = fmaxf(mA, __shfl_xor_sync(0xffffffffu, mA, 2));
        mB = fmaxf(mB, __shfl_xor_sync(0xffffffffu, mB, 1));
        mB = fmaxf(mB, __shfl_xor_sync(0xffffffffu, mB, 2));
        float sA = 0.f, sB = 0.f;
        #pragma unroll
        for (int i = 0; i < 10; ++i) { sA += __expf(lg[0][i] - mA); sB += __expf(lg[1][i] - mB); }
        sA += __shfl_xor_sync(0xffffffffu, sA, 1);
        sA += __shfl_xor_sync(0xffffffffu, sA, 2);
        sB += __shfl_xor_sync(0xffffffffu, sB, 1);
        sB += __shfl_xor_sync(0xffffffffu, sB, 2);
        const float lseA = mA + __logf(sA);
        const float lseB = mB + __logf(sB);

        const int rA = 16 * warp + (lane >> 2);
        float* rowA = out + ((size_t)blockIdx.x * NODES_PER_BLOCK + rA) * NCLS + (lane & 3) * 2;
        float* rowB = rowA + 8 * NCLS;
        #pragma unroll
        for (int nt = 0; nt < 5; ++nt) {
            float2 oA, oB;
            oA.x = lg[0][2 * nt]     - lseA;
            oA.y = lg[0][2 * nt + 1] - lseA;
            oB.x = lg[1][2 * nt]     - lseB;
            oB.y = lg[1][2 * nt + 1] - lseB;
            *(float2*)(rowA + nt * 8) = oA;
            *(float2*)(rowB + nt * 8) = oB;
        }
    }
}

extern "C" void kernel_launch(void* const* d_in, const int* in_sizes, int n_in,
                              void* d_out, int out_size) {
    const float* x  = (const float*)d_in[0];
    const void*  nb = d_in[1];
    const float* cw = (const float*)d_in[2];
    const float* cb = (const float*)d_in[3];
    const float* gw = (const float*)d_in[4];
    const float* gb = (const float*)d_in[5];
    const float* ow = (const float*)d_in[6];
    const float* ob = (const float*)d_in[7];
    float* out = (float*)d_out;

    cudaFuncSetAttribute(main_kernel, cudaFuncAttributeMaxDynamicSharedMemorySize, SMEM_BYTES);

    prologue_kernel<<<PRO_BLOCKS, 256>>>((const float4*)x, cw, cb, gw, gb, ow, ob,
                                         (const unsigned int*)nb);
    main_kernel<<<N_NODES / NODES_PER_BLOCK, THREADS, SMEM_BYTES>>>(nb, out);
}

// round 17
// speedup vs baseline: 1.0945x; 1.0945x over previous
#include <cuda_runtime.h>
#include <cuda_fp16.h>
#include <cstdint>

#define N_NODES 262144
#define C 64
#define K 16
#define NCLS 40

#define WARPS 16
#define THREADS (WARPS * 32)
#define NODES_PER_BLOCK 128
#define NODES_PER_WARP 8

// ---- A-fragment feat storage: 16 ktiles (h:0-7, rel:8-15), 128r x 8c fp16, pad 2064 ----
#define KTS 2064
#define SMEM_BYTES (16 * KTS)       // 33024

// prologue grid split
#define CPE_BLOCKS 2048
#define FUSE_BLOCKS 21
#define PRO_BLOCKS (CPE_BLOCKS + FUSE_BLOCKS + 1)

// ---- device scratch (allocation-free rule) ----
__device__ __align__(256) static __half d_hh[N_NODES * C];     // 32 MB fp16 h (L2-resident)
__device__ __align__(8)  static float d_bf[NCLS];
// fp16 k16 B fragments: cell=(kt2*5+nt)*32+lane, 4 u16/cell
__device__ __align__(16) static uint16_t d_Bfrag[1280 * 4];    // 10240 B
__device__ static int d_idx64;

// ---------- helpers ----------
__device__ __forceinline__ void mma16f(float* c, uint32_t a0, uint32_t a1, uint32_t a2,
                                       uint32_t a3, uint32_t b0, uint32_t b1) {
    asm volatile("mma.sync.aligned.m16n8k16.row.col.f32.f16.f16.f32 "
                 "{%0,%1,%2,%3}, {%4,%5,%6,%7}, {%8,%9}, {%0,%1,%2,%3};"
                 : "+f"(c[0]), "+f"(c[1]), "+f"(c[2]), "+f"(c[3])
                 : "r"(a0), "r"(a1), "r"(a2), "r"(a3), "r"(b0), "r"(b1));
}
__device__ __forceinline__ uint32_t h2max_u(uint32_t a, uint32_t b) {
    uint32_t r;
    asm("max.f16x2 %0, %1, %2;" : "=r"(r) : "r"(a), "r"(b));
    return r;
}
__device__ __forceinline__ uint32_t h2sub_u(uint32_t a, uint32_t b) {
    uint32_t r;
    asm("sub.rn.f16x2 %0, %1, %2;" : "=r"(r) : "r"(a), "r"(b));
    return r;
}
__device__ __forceinline__ void bar_arrive(int id, int cnt) {
    asm volatile("bar.arrive %0, %1;" :: "r"(id), "r"(cnt) : "memory");
}
__device__ __forceinline__ void bar_sync(int id, int cnt) {
    asm volatile("bar.sync %0, %1;" :: "r"(id), "r"(cnt) : "memory");
}

// ---------- prologue: CPE (blocks 0..2047) + fuse_w (21 blocks) + detect (1) ----------
__global__ void prologue_kernel(const float4* __restrict__ x4,
                                const float* __restrict__ cw,
                                const float* __restrict__ cb,
                                const float* __restrict__ gw,
                                const float* __restrict__ gb,
                                const float* __restrict__ ow,
                                const float* __restrict__ ob,
                                const unsigned int* __restrict__ nbrw) {
    if (blockIdx.x < CPE_BLOCKS) {
        // ---- CPE depthwise conv (kernel 3 over node dim) + residual; fp16 output ----
        const int idx = blockIdx.x * 256 + threadIdx.x;
        const int q = idx & 15;
        const int n0 = (idx >> 4) * 8;
        const int c0 = q * 4;
        const float w0x = __ldg(cw + (c0+0)*3+0), w1x = __ldg(cw + (c0+0)*3+1), w2x = __ldg(cw + (c0+0)*3+2);
        const float w0y = __ldg(cw + (c0+1)*3+0), w1y = __ldg(cw + (c0+1)*3+1), w2y = __ldg(cw + (c0+1)*3+2);
        const float w0z = __ldg(cw + (c0+2)*3+0), w1z = __ldg(cw + (c0+2)*3+1), w2z = __ldg(cw + (c0+2)*3+2);
        const float w0w = __ldg(cw + (c0+3)*3+0), w1w = __ldg(cw + (c0+3)*3+1), w2w = __ldg(cw + (c0+3)*3+2);
        const float bx = __ldg(cb+c0+0), by = __ldg(cb+c0+1), bz = __ldg(cb+c0+2), bw = __ldg(cb+c0+3);

        const float4 zero = make_float4(0.f, 0.f, 0.f, 0.f);
        float4 a = (n0 > 0) ? __ldcs(x4 + (n0 - 1) * 16 + q) : zero;
        float4 b = __ldcs(x4 + n0 * 16 + q);
        uint2* hh2 = reinterpret_cast<uint2*>(d_hh);
        #pragma unroll
        for (int r = 0; r < 8; ++r) {
            const int n = n0 + r;
            const float4 nx = (n + 1 < N_NODES) ? __ldcs(x4 + (n + 1) * 16 + q) : zero;
            float4 o;
            o.x = b.x + (a.x*w0x + b.x*w1x + nx.x*w2x + bx);
            o.y = b.y + (a.y*w0y + b.y*w1y + nx.y*w2y + by);
            o.z = b.z + (a.z*w0z + b.z*w1z + nx.z*w2z + bz);
            o.w = b.w + (a.w*w0w + b.w*w1w + nx.w*w2w + bw);
            const __half2 p0 = __floats2half2_rn(o.x, o.y);
            const __half2 p1 = __floats2half2_rn(o.z, o.w);
            uint2 u;
            u.x = *reinterpret_cast<const uint32_t*>(&p0);
            u.y = *reinterpret_cast<const uint32_t*>(&p1);
            hh2[n * 16 + q] = u;
            a = b; b = nx;
        }
        return;
    }
    if (blockIdx.x == CPE_BLOCKS + FUSE_BLOCKS) {
        // ---- detect whether nbr_idx is int64 (odd 32-bit words all zero) ----
        __shared__ int any;
        if (threadIdx.x == 0) any = 0;
        __syncthreads();
        if (nbrw[2 * threadIdx.x + 1] != 0u) any = 1;
        __syncthreads();
        if (threadIdx.x == 0) d_idx64 = (any ? 0 : 1);
        return;
    }
    // ---- fuse grapher into head; emit fp16 k16 B-fragment cells ----
    const int t = (blockIdx.x - CPE_BLOCKS) * 256 + threadIdx.x;
    if (t < 2 * C * NCLS) {
        const int c = t / NCLS, j = t % NCLS;
        float acc = (c < C) ? ow[c * NCLS + j] : 0.f;
        #pragma unroll 8
        for (int d = 0; d < C; ++d) acc += gw[c * C + d] * ow[d * NCLS + j];
        const int kt2 = c >> 4, pairw = (c >> 3) & 1, nt = j >> 3;
        const int lane = (j & 7) * 4 + ((c & 7) >> 1);
        const int cell = (kt2 * 5 + nt) * 32 + lane;
        const __half hv = __float2half(acc);
        d_Bfrag[cell * 4 + pairw * 2 + (c & 1)] = *reinterpret_cast<const uint16_t*>(&hv);
    } else if (t < 2 * C * NCLS + NCLS) {
        const int j = t - 2 * C * NCLS;
        float acc = ob[j];
        for (int d = 0; d < C; ++d) acc += gb[d] * ow[d * NCLS + j];
        d_bf[j] = acc;
    }
}

// ---------- main kernel: fp16 gather -> pairwise barriers -> mma f16 -> log_softmax ----------
__global__ __launch_bounds__(THREADS, 2) void main_kernel(const void* __restrict__ nbr,
                                                          float* __restrict__ out) {
    extern __shared__ __align__(16) char smem[];
    const int tid = threadIdx.x;
    const int warp = tid >> 5, lane = tid & 31;
    const __half* __restrict__ HH = d_hh;

    // ---- gather: half-warp = 1 node; lane owns channel quad q = lane&15 ----
    const int nodeBase = blockIdx.x * NODES_PER_BLOCK + warp * NODES_PER_WARP;
    const int is64 = d_idx64;
    const int q = lane & 15;
    const int half = lane >> 4;
    const int n0 = nodeBase + half;

    int idxs[4];
    if (is64) {
        const long long* p = (const long long*)nbr + (size_t)n0 * K + q;
        #pragma unroll
        for (int t = 0; t < 4; ++t) idxs[t] = (int)__ldcg(p + 2 * t * K);
    } else {
        const int* p = (const int*)nbr + n0 * K + q;
        #pragma unroll
        for (int t = 0; t < 4; ++t) idxs[t] = __ldcg(p + 2 * t * K);
    }

    const uint32_t baseC = (uint32_t)(q >> 1) * KTS
                         + (uint32_t)((warp >> 1) * 2 + (warp & 1)) * 128
                         + (uint32_t)(half * 4 + (q & 1) * 2) * 4;

    #pragma unroll
    for (int t = 0; t < 4; ++t) {
        const int myj = idxs[t];
        const uint2 hv = __ldcg((const uint2*)(HH + (n0 + 2 * t) * C) + q);
        const uint32_t ninf = 0xFBFFFBFFu;   // half2(-65504, -65504)
        uint32_t m0a = ninf, m0b = ninf, m1a = ninf, m1b = ninf;
        #pragma unroll
        for (int k = 0; k < K; k += 2) {
            const int j0 = __shfl_sync(0xffffffffu, myj, k, 16);
            const int j1 = __shfl_sync(0xffffffffu, myj, k + 1, 16);
            const uint2 u0 = __ldcg((const uint2*)(HH + j0 * C + q * 4));
            const uint2 u1 = __ldcg((const uint2*)(HH + j1 * C + q * 4));
            m0a = h2max_u(m0a, u0.x); m0b = h2max_u(m0b, u0.y);
            m1a = h2max_u(m1a, u1.x); m1b = h2max_u(m1b, u1.y);
        }
        uint2 rel;
        rel.x = h2sub_u(h2max_u(m0a, m1a), hv.x);
        rel.y = h2sub_u(h2max_u(m0b, m1b), hv.y);

        const uint32_t base = baseC + (uint32_t)t * 32;
        *(uint2*)(smem + base)           = hv;      // ktiles 0..7  (h, exact)
        *(uint2*)(smem + 8 * KTS + base) = rel;     // ktiles 8..15 (rel)
    }

    // ---- pairwise sync: MMA warp w consumes gather warps {2w, 2w+1} only ----
    // barrier id 1+w; count 64 for w=0 (warps 0,1), else 96 (warps w, 2w, 2w+1)
    {
        const int wc = warp >> 1;                 // consumer fed by this gather warp
        if (warp == 0) {
            bar_sync(1, 64);                      // arrive+wait (producer==consumer)
        } else {
            __threadfence_block();                // make feat stores visible
            bar_arrive(1 + wc, (wc == 0) ? 64 : 96);
            if (warp < 8) bar_sync(1 + warp, 96); // own consumer barrier
        }
    }

    // ---- MMA: warps 0-7, m16n8k16 fp16; B frags via L1 LDG.64; direct-STG epilogue ----
    if (warp < 8) {
        float acc[5][4];
        #pragma unroll
        for (int nt = 0; nt < 5; ++nt)
            #pragma unroll
            for (int p = 0; p < 4; ++p) acc[nt][p] = 0.f;

        const char* fa = smem + (warp * 2) * 128 + lane * 4;
        const uint2* Bq = reinterpret_cast<const uint2*>(d_Bfrag) + lane;
        #pragma unroll
        for (int kt2 = 0; kt2 < 8; ++kt2) {
            const uint32_t a0 = *(const uint32_t*)(fa + (2 * kt2) * KTS);
            const uint32_t a1 = *(const uint32_t*)(fa + (2 * kt2) * KTS + 128);
            const uint32_t a2 = *(const uint32_t*)(fa + (2 * kt2 + 1) * KTS);
            const uint32_t a3 = *(const uint32_t*)(fa + (2 * kt2 + 1) * KTS + 128);
            #pragma unroll
            for (int nt = 0; nt < 5; ++nt) {
                const uint2 w = __ldg(Bq + (kt2 * 5 + nt) * 32);
                mma16f(acc[nt], a0, a1, a2, a3, w.x, w.y);
            }
        }

        // bias + per-row log_softmax (rows: rA = 16w + lane/4, rB = rA + 8)
        float lg[2][10];
        #pragma unroll
        for (int nt = 0; nt < 5; ++nt) {
            const float2 b = __ldg(reinterpret_cast<const float2*>(d_bf) + nt * 4 + (lane & 3));
            lg[0][2 * nt]     = acc[nt][0] + b.x;
            lg[0][2 * nt + 1] = acc[nt][1] + b.y;
            lg[1][2 * nt]     = acc[nt][2] + b.x;
            lg[1][2 * nt + 1] = acc[nt][3] + b.y;
        }
        float mA = lg[0][0], mB = lg[1][0];
        #pragma unroll
        for (int i = 1; i < 10; ++i) { mA = fmaxf(mA, lg[0][i]); mB = fmaxf(mB, lg[1][i]); }
        mA = fmaxf(mA, __shfl_xor_sync(0xffffffffu, mA, 1));
        mA = fmaxf(mA, __shfl_xor_sync(0xffffffffu, mA, 2));
        mB = fmaxf(mB, __shfl_xor_sync(0xffffffffu, mB, 1));
        mB = fmaxf(mB, __shfl_xor_sync(0xffffffffu, mB, 2));
        float sA = 0.f, sB = 0.f;
        #pragma unroll
        for (int i = 0; i < 10; ++i) { sA += __expf(lg[0][i] - mA); sB += __expf(lg[1][i] - mB); }
        sA += __shfl_xor_sync(0xffffffffu, sA, 1);
        sA += __shfl_xor_sync(0xffffffffu, sA, 2);
        sB += __shfl_xor_sync(0xffffffffu, sB, 1);
        sB += __shfl_xor_sync(0xffffffffu, sB, 2);
        const float lseA = mA + __logf(sA);
        const float lseB = mB + __logf(sB);

        const int rA = 16 * warp + (lane >> 2);
        float* rowA = out + ((size_t)blockIdx.x * NODES_PER_BLOCK + rA) * NCLS + (lane & 3) * 2;
        float* rowB = rowA + 8 * NCLS;
        #pragma unroll
        for (int nt = 0; nt < 5; ++nt) {
            float2 oA, oB;
            oA.x = lg[0][2 * nt]     - lseA;
            oA.y = lg[0][2 * nt + 1] - lseA;
            oB.x = lg[1][2 * nt]     - lseB;
            oB.y = lg[1][2 * nt + 1] - lseB;
            *(float2*)(rowA + nt * 8) = oA;
            *(float2*)(rowB + nt * 8) = oB;
        }
    }
}

extern "C" void kernel_launch(void* const* d_in, const int* in_sizes, int n_in,
                              void* d_out, int out_size) {
    const float* x  = (const float*)d_in[0];
    const void*  nb = d_in[1];
    const float* cw = (const float*)d_in[2];
    const float* cb = (const float*)d_in[3];
    const float* gw = (const float*)d_in[4];
    const float* gb = (const float*)d_in[5];
    const float* ow = (const float*)d_in[6];
    const float* ob = (const float*)d_in[7];
    float* out = (float*)d_out;

    cudaFuncSetAttribute(main_kernel, cudaFuncAttributeMaxDynamicSharedMemorySize, SMEM_BYTES);

    prologue_kernel<<<PRO_BLOCKS, 256>>>((const float4*)x, cw, cb, gw, gb, ow, ob,
                                         (const unsigned int*)nb);
    main_kernel<<<N_NODES / NODES_PER_BLOCK, THREADS, SMEM_BYTES>>>(nb, out);
}